// round 1
// baseline (speedup 1.0000x reference)
#include <cuda_runtime.h>

// Problem constants
constexpr int C_DIM  = 512;      // model dim
constexpr int NHEADS = 8;
constexpr int HD     = 64;       // head dim
constexpr int NB     = 8;        // batch
constexpr int NSEQ   = 1024;     // sequence length
constexpr int M_TOT  = NB * NSEQ;   // 8192 rows for the KV GEMM
constexpr int KVN    = 2 * C_DIM;   // 1024 output cols of the KV GEMM
constexpr float SCALE = 0.125f;     // 64^-0.5

// Scratch for kv1 / kv2: [2][B*N, 1024]  (64 MB static device memory)
__device__ float g_kv[2][(size_t)M_TOT * KVN];

// ---------------------------------------------------------------------------
// Kernel 1: kv = x @ W   (two independent GEMMs, blockIdx.z selects branch)
// X: [8192, 512] row-major, W: [512, 1024] row-major, C: [8192, 1024]
// 128x128 tile, BK=8, 256 threads, 8x8 per-thread register blocking.
// ---------------------------------------------------------------------------
__global__ __launch_bounds__(256) void kv_gemm(const float* __restrict__ x1,
                                               const float* __restrict__ x2,
                                               const float* __restrict__ w1,
                                               const float* __restrict__ w2) {
    const int br = blockIdx.z;
    const float* __restrict__ X = br ? x2 : x1;
    const float* __restrict__ W = br ? w2 : w1;
    float* __restrict__ Cout = g_kv[br];

    __shared__ float As[8][132];   // transposed A tile: As[k][m]; pitch 132 -> conflict-free STS
    __shared__ float Bs[8][128];   // B tile row-major

    const int t  = threadIdx.x;
    const int tx = t & 15;
    const int ty = t >> 4;
    const int m0 = blockIdx.y * 128;
    const int n0 = blockIdx.x * 128;

    const int arow = t >> 1;            // 0..127
    const int ac4  = (t & 1) * 4;       // 0 or 4
    const int brow = t >> 5;            // 0..7
    const int bc4  = (t & 31) * 4;      // 0..124

    float acc[8][8] = {};

    for (int k0 = 0; k0 < C_DIM; k0 += 8) {
        const float4 av = *(const float4*)&X[(size_t)(m0 + arow) * C_DIM + k0 + ac4];
        const float4 bv = *(const float4*)&W[(size_t)(k0 + brow) * KVN + n0 + bc4];
        __syncthreads();   // previous iteration's reads complete before overwrite
        As[ac4 + 0][arow] = av.x;
        As[ac4 + 1][arow] = av.y;
        As[ac4 + 2][arow] = av.z;
        As[ac4 + 3][arow] = av.w;
        *(float4*)&Bs[brow][bc4] = bv;
        __syncthreads();

        #pragma unroll
        for (int kk = 0; kk < 8; kk++) {
            float a[8], b[8];
            #pragma unroll
            for (int i = 0; i < 4; i++) {
                const float4 v0 = *(const float4*)&As[kk][ty * 8 + 4 * (i >> 1)];
                // unpack two halves via two vec4 loads instead:
                (void)v0;
            }
            {
                const float4 a0 = *(const float4*)&As[kk][ty * 8 + 0];
                const float4 a1 = *(const float4*)&As[kk][ty * 8 + 4];
                a[0] = a0.x; a[1] = a0.y; a[2] = a0.z; a[3] = a0.w;
                a[4] = a1.x; a[5] = a1.y; a[6] = a1.z; a[7] = a1.w;
                const float4 b0 = *(const float4*)&Bs[kk][tx * 8 + 0];
                const float4 b1 = *(const float4*)&Bs[kk][tx * 8 + 4];
                b[0] = b0.x; b[1] = b0.y; b[2] = b0.z; b[3] = b0.w;
                b[4] = b1.x; b[5] = b1.y; b[6] = b1.z; b[7] = b1.w;
            }
            #pragma unroll
            for (int i = 0; i < 8; i++)
                #pragma unroll
                for (int j = 0; j < 8; j++)
                    acc[i][j] = fmaf(a[i], b[j], acc[i][j]);
        }
    }

    #pragma unroll
    for (int i = 0; i < 8; i++) {
        const size_t row = (size_t)(m0 + ty * 8 + i) * KVN + n0 + tx * 8;
        float4 v0 = {acc[i][0], acc[i][1], acc[i][2], acc[i][3]};
        float4 v1 = {acc[i][4], acc[i][5], acc[i][6], acc[i][7]};
        *(float4*)&Cout[row + 0] = v0;
        *(float4*)&Cout[row + 4] = v1;
    }
}

// ---------------------------------------------------------------------------
// Kernel 2: fused cross attention (no softmax — relu of scaled scores).
// branch 0: out1 = relu(q1 k2^T * s) @ v1     branch 1: out2 = relu(q2 k1^T * s) @ v2
// CTA = (q-tile of 64 rows, b*h, branch). Loops 16 kv tiles of 64 rows.
// 256 threads, 4x4 per-thread blocking for both GEMM stages.
// smem: q[64][64], kT/s aliased [64][64], v[64][64] = 48 KB.
// ---------------------------------------------------------------------------
__global__ __launch_bounds__(256) void attn_kernel(const float* __restrict__ x1,
                                                   const float* __restrict__ x2,
                                                   float* __restrict__ out) {
    const int br = blockIdx.z;
    const int bh = blockIdx.y;
    const int bb = bh >> 3;
    const int hh = bh & 7;
    const int qt = blockIdx.x;

    const float* __restrict__ q_g = (br ? x2 : x1)
        + (size_t)bb * NSEQ * C_DIM + (size_t)qt * 64 * C_DIM + hh * HD;
    const float* __restrict__ k_g = g_kv[1 - br] + (size_t)bb * NSEQ * KVN + hh * HD;
    const float* __restrict__ v_g = g_kv[br] + (size_t)bb * NSEQ * KVN + C_DIM + hh * HD;
    float* __restrict__ o_g = out + (size_t)br * NB * NSEQ * C_DIM
        + (size_t)bb * NSEQ * C_DIM + (size_t)qt * 64 * C_DIM + hh * HD;

    __shared__ float q_s[64][64];   // q[i][d]
    __shared__ float ks_s[64][64];  // stage1: kT[d][j];  stage2 (aliased): S[i][j]
    __shared__ float v_s[64][64];   // v[m][d]

    const int t  = threadIdx.x;
    const int tx = t & 15;
    const int ty = t >> 4;

    // Load q tile once (coalesced vec4)
    #pragma unroll
    for (int l = 0; l < 4; l++) {
        const int V  = t + l * 256;
        const int i  = V >> 4;
        const int c4 = (V & 15) << 2;
        *(float4*)&q_s[i][c4] = *(const float4*)&q_g[(size_t)i * C_DIM + c4];
    }

    float o_acc[4][4] = {};

    for (int mt = 0; mt < 16; mt++) {
        __syncthreads();   // prior stage2 reads of ks_s / v_s done (also covers q_s on mt=0)

        // Load k transposed: lane-per-row mapping -> conflict-free scalar STS
        #pragma unroll
        for (int l = 0; l < 4; l++) {
            const int V  = t + l * 256;
            const int j  = V & 63;
            const int d0 = (V >> 6) << 2;
            const float4 kv4 = *(const float4*)&k_g[(size_t)(mt * 64 + j) * KVN + d0];
            ks_s[d0 + 0][j] = kv4.x;
            ks_s[d0 + 1][j] = kv4.y;
            ks_s[d0 + 2][j] = kv4.z;
            ks_s[d0 + 3][j] = kv4.w;
        }
        // Load v (coalesced vec4, row-major)
        #pragma unroll
        for (int l = 0; l < 4; l++) {
            const int V  = t + l * 256;
            const int m  = V >> 4;
            const int c4 = (V & 15) << 2;
            *(float4*)&v_s[m][c4] = *(const float4*)&v_g[(size_t)(mt * 64 + m) * KVN + c4];
        }
        __syncthreads();

        // Stage 1: S[a][b] = sum_d q[4ty+a][d] * k[4tx+b][d]
        float s_acc[4][4] = {};
        #pragma unroll
        for (int d0 = 0; d0 < 64; d0 += 4) {
            float4 qv[4], kv[4];
            #pragma unroll
            for (int a = 0; a < 4; a++) qv[a] = *(const float4*)&q_s[ty * 4 + a][d0];
            #pragma unroll
            for (int dd = 0; dd < 4; dd++) kv[dd] = *(const float4*)&ks_s[d0 + dd][tx * 4];
            #pragma unroll
            for (int a = 0; a < 4; a++) {
                const float qa[4] = {qv[a].x, qv[a].y, qv[a].z, qv[a].w};
                #pragma unroll
                for (int dd = 0; dd < 4; dd++) {
                    s_acc[a][0] = fmaf(qa[dd], kv[dd].x, s_acc[a][0]);
                    s_acc[a][1] = fmaf(qa[dd], kv[dd].y, s_acc[a][1]);
                    s_acc[a][2] = fmaf(qa[dd], kv[dd].z, s_acc[a][2]);
                    s_acc[a][3] = fmaf(qa[dd], kv[dd].w, s_acc[a][3]);
                }
            }
        }
        __syncthreads();   // all kT reads done before aliasing with S

        // relu + scale, stage S through the kT buffer
        #pragma unroll
        for (int a = 0; a < 4; a++) {
            float4 sv;
            sv.x = fmaxf(s_acc[a][0], 0.0f) * SCALE;
            sv.y = fmaxf(s_acc[a][1], 0.0f) * SCALE;
            sv.z = fmaxf(s_acc[a][2], 0.0f) * SCALE;
            sv.w = fmaxf(s_acc[a][3], 0.0f) * SCALE;
            *(float4*)&ks_s[ty * 4 + a][tx * 4] = sv;
        }
        __syncthreads();

        // Stage 2: o[a][b] += sum_m S[4ty+a][m] * v[m][4tx+b]
        #pragma unroll
        for (int m0 = 0; m0 < 64; m0 += 4) {
            float4 sv[4], vv[4];
            #pragma unroll
            for (int a = 0; a < 4; a++) sv[a] = *(const float4*)&ks_s[ty * 4 + a][m0];
            #pragma unroll
            for (int mm = 0; mm < 4; mm++) vv[mm] = *(const float4*)&v_s[m0 + mm][tx * 4];
            #pragma unroll
            for (int a = 0; a < 4; a++) {
                const float sa[4] = {sv[a].x, sv[a].y, sv[a].z, sv[a].w};
                #pragma unroll
                for (int mm = 0; mm < 4; mm++) {
                    o_acc[a][0] = fmaf(sa[mm], vv[mm].x, o_acc[a][0]);
                    o_acc[a][1] = fmaf(sa[mm], vv[mm].y, o_acc[a][1]);
                    o_acc[a][2] = fmaf(sa[mm], vv[mm].z, o_acc[a][2]);
                    o_acc[a][3] = fmaf(sa[mm], vv[mm].w, o_acc[a][3]);
                }
            }
        }
    }

    #pragma unroll
    for (int a = 0; a < 4; a++) {
        float4 ov = {o_acc[a][0], o_acc[a][1], o_acc[a][2], o_acc[a][3]};
        *(float4*)&o_g[(size_t)(ty * 4 + a) * C_DIM + tx * 4] = ov;
    }
}

// ---------------------------------------------------------------------------
extern "C" void kernel_launch(void* const* d_in, const int* in_sizes, int n_in,
                              void* d_out, int out_size) {
    const float* x1 = (const float*)d_in[0];
    const float* x2 = (const float*)d_in[1];
    const float* w1 = (const float*)d_in[2];
    const float* w2 = (const float*)d_in[3];
    float* out = (float*)d_out;

    dim3 g1(KVN / 128, M_TOT / 128, 2);     // (8, 64, 2)
    kv_gemm<<<g1, 256>>>(x1, x2, w1, w2);

    dim3 g2(NSEQ / 64, NB * NHEADS, 2);     // (16, 64, 2)
    attn_kernel<<<g2, 256>>>(x1, x2, out);
}